// round 8
// baseline (speedup 1.0000x reference)
#include <cuda_runtime.h>
#include <cuda_bf16.h>
#include <cstdint>

// Correlation cost volume:
// out[b, 9*i+j, h, w] = (1/C) * sum_c x1[b,c,h,w] * x2[b,c,h+i-4,w+j-4]
// B=4, C=256, H=96, W=192, 9x9 grid, zero padding.
// R7: R2 layout (TW=32, 16B cp.async, conflict-free LDS.128) with
//   - CH=16 chunks, ONE __syncthreads per iteration
//   - even dj: packed FFMA2 on natural pairs; odd dj: scalar FFMA (no MOVs)
//   - affine single-job loader

#define B_ 4
#define C_ 256
#define H_ 96
#define W_ 192
#define HW_ (H_ * W_)
#define TH 4
#define TW 32
#define PW 4
#define CH 16
#define NCHUNK (C_ / CH)            // 16
#define X2ROWS 12
#define X2STR 56                    // conflict-free LDS.128
#define X1STR 40                    // conflict-free LDS.128
#define X2BUF (CH * X2ROWS * X2STR)     // 10752 floats
#define X1BUF (CH * TH * X1STR)         // 2560 floats
#define SMEM_FLOATS (2 * X2BUF + 2 * X1BUF)   // 26624 floats = 106496 B
#define NTHREADS 288
#define CHUNK_ELEMS (CH * HW_)
#define X2CHSTRB (X2ROWS * X2STR * 4)   // 2688 B per channel
#define X1CHSTRB (TH * X1STR * 4)       // 640 B per channel
#define X2BUFB (X2BUF * 4)
#define X1BUFB (X1BUF * 4)

typedef unsigned long long ull;

__device__ __forceinline__ void cp_async16(uint32_t dst, const float* src, int sz) {
    asm volatile("cp.async.cg.shared.global [%0], [%1], 16, %2;\n"
                 :: "r"(dst), "l"(src), "r"(sz));
}
__device__ __forceinline__ void cp_commit() {
    asm volatile("cp.async.commit_group;\n");
}
__device__ __forceinline__ void cp_wait0() {
    asm volatile("cp.async.wait_group 0;\n");
}
__device__ __forceinline__ void fma2(ull& acc, ull a, ull b) {
    asm("fma.rn.f32x2 %0, %1, %2, %0;" : "+l"(acc) : "l"(a), "l"(b));
}
__device__ __forceinline__ void mul2(ull& acc, ull s) {
    asm("mul.rn.f32x2 %0, %0, %1;" : "+l"(acc) : "l"(s));
}
__device__ __forceinline__ float LOF(ull v) { return __uint_as_float((uint32_t)v); }
__device__ __forceinline__ float HIF(ull v) { return __uint_as_float((uint32_t)(v >> 32)); }

__global__ __launch_bounds__(NTHREADS, 2)
void corr_kernel(const float* __restrict__ x1,
                 const float* __restrict__ x2,
                 float* __restrict__ out) {
    extern __shared__ float smem[];
    float* sx2 = smem;                 // [2][CH][12][56]
    float* sx1 = smem + 2 * X2BUF;     // [2][CH][4][40]

    const int w0 = blockIdx.x * TW;
    const int h0 = blockIdx.y * TH;
    const int b  = blockIdx.z;

    const int tid  = threadIdx.x;
    const int di   = tid >> 5;
    const int lane = tid & 31;
    const int r    = lane & 3;
    const int wg   = lane >> 2;
    const int wbase = wg * PW;
    const int rdi  = r + di;

    const float* x1g = x1 + (size_t)b * C_ * HW_;
    const float* x2g = x2 + (size_t)b * C_ * HW_;

    const uint32_t sx2_u = (uint32_t)__cvta_generic_to_shared(sx2);
    const uint32_t sx1_u = (uint32_t)__cvta_generic_to_shared(sx1);

    // ---------------- affine loader precompute ----------------
    // x2: 2304 jobs = CH*12 rows x 12 float4. qid = tid + 288*s, 288 = 24*12:
    //   q = tid%12, rowid = tid/12 + 24*s -> rr = (tid/12)%12, c = (tid/12)/12 + 2s.
    const int r0  = tid / 12;          // 0..23
    const int qx  = tid - r0 * 12;     // 0..11
    const int c0  = r0 / 12;           // 0..1
    const int rr  = r0 - c0 * 12;      // 0..11
    const int gh  = h0 + rr - 4;
    const int gw0 = w0 - 8 + 4 * qx;
    const bool ok = ((unsigned)gh < (unsigned)H_) && (gw0 >= 0) && (gw0 <= W_ - 4);
    const int x2size = ok ? 16 : 0;
    const float* x2s0 = ok ? (x2g + ((size_t)c0 * H_ + gh) * W_ + gw0)
                           : x2g;
    const uint32_t x2d0 = sx2_u + (uint32_t)(((c0 * X2ROWS + rr) * X2STR + 4 * qx) * 4);

    // x1: 512 jobs = CH*4 rows x 8 float4, threads 0..255 take u=0,1:
    //   c = tid/32 + 8u, rr1 = (tid/8)%4, q1 = tid%8
    const bool do_x1 = (tid < 256);
    const int c1  = tid >> 5;
    const int rr1 = (tid >> 3) & 3;
    const int q1  = tid & 7;
    const float* x1s0 = x1g + ((size_t)c1 * H_ + (h0 + rr1)) * W_ + w0 + 4 * q1;
    const uint32_t x1d0 = sx1_u + (uint32_t)(((c1 * TH + rr1) * X1STR + 4 * q1) * 4);

    auto issue_chunk = [&](int ck, int bb) {
        const int chOff = ck * CHUNK_ELEMS;
        const float* s2 = x2s0 + chOff;
        uint32_t d2 = x2d0 + (uint32_t)bb * X2BUFB;
        #pragma unroll
        for (int s = 0; s < 8; ++s) {
            cp_async16(d2, s2, x2size);
            s2 += 2 * HW_;
            d2 += 2 * X2CHSTRB;
        }
        if (do_x1) {
            const float* s1 = x1s0 + chOff;
            uint32_t d1 = x1d0 + (uint32_t)bb * X1BUFB;
            cp_async16(d1, s1, 16);
            cp_async16(d1 + 8 * X1CHSTRB, s1 + 8 * HW_, 16);
        }
    };

    // ---------------- accumulators ----------------
    ull  eacc[5][2];     // even dj (0,2,4,6,8) x pixel-pair (01, 23)
    float sacc[4][4];    // odd  dj (1,3,5,7)  x pixel (0..3)
    #pragma unroll
    for (int m = 0; m < 5; ++m) { eacc[m][0] = 0ull; eacc[m][1] = 0ull; }
    #pragma unroll
    for (int m = 0; m < 4; ++m)
        #pragma unroll
        for (int k = 0; k < 4; ++k) sacc[m][k] = 0.0f;

    // ---------------- prologue ----------------
    issue_chunk(0, 0);
    cp_commit();

    // ---------------- main loop: ONE sync per iteration ----------------
    for (int it = 0; it < NCHUNK; ++it) {
        cp_wait0();          // own copies for chunk `it` done
        __syncthreads();     // everyone's copies visible; buf (it+1)&1 free
        if (it + 1 < NCHUNK) {
            issue_chunk(it + 1, (it + 1) & 1);
            cp_commit();
        }

        const float* cx1 = sx1 + (it & 1) * X1BUF + r * X1STR + wbase;
        const float* cx2 = sx2 + (it & 1) * X2BUF + rdi * X2STR + (wbase + 4);

        #pragma unroll
        for (int c = 0; c < CH; ++c) {
            const ulonglong2 A  = *reinterpret_cast<const ulonglong2*>(cx1 + c * (TH * X1STR));
            const ulonglong2 E0 = *reinterpret_cast<const ulonglong2*>(cx2 + c * (X2ROWS * X2STR));
            const ulonglong2 E1 = *reinterpret_cast<const ulonglong2*>(cx2 + c * (X2ROWS * X2STR) + 4);
            const ulonglong2 E2 = *reinterpret_cast<const ulonglong2*>(cx2 + c * (X2ROWS * X2STR) + 8);
            const ull a0 = A.x,  a1 = A.y;
            const ull e0 = E0.x, e1 = E0.y;
            const ull e2 = E1.x, e3 = E1.y;
            const ull e4 = E2.x, e5 = E2.y;

            // even dj = 2m: natural pairs e_m, e_{m+1}
            fma2(eacc[0][0], a0, e0); fma2(eacc[0][1], a1, e1);
            fma2(eacc[1][0], a0, e1); fma2(eacc[1][1], a1, e2);
            fma2(eacc[2][0], a0, e2); fma2(eacc[2][1], a1, e3);
            fma2(eacc[3][0], a0, e3); fma2(eacc[3][1], a1, e4);
            fma2(eacc[4][0], a0, e4); fma2(eacc[4][1], a1, e5);

            // odd dj = 2m+1: scalar FFMA on free half-register refs
            const float as0 = LOF(a0), as1 = HIF(a0), as2 = LOF(a1), as3 = HIF(a1);
            const float xs1 = HIF(e0), xs2 = LOF(e1), xs3 = HIF(e1), xs4 = LOF(e2);
            const float xs5 = HIF(e2), xs6 = LOF(e3), xs7 = HIF(e3), xs8 = LOF(e4);
            const float xs9 = HIF(e4), xs10 = LOF(e5);
            sacc[0][0] = fmaf(as0, xs1,  sacc[0][0]);
            sacc[0][1] = fmaf(as1, xs2,  sacc[0][1]);
            sacc[0][2] = fmaf(as2, xs3,  sacc[0][2]);
            sacc[0][3] = fmaf(as3, xs4,  sacc[0][3]);
            sacc[1][0] = fmaf(as0, xs3,  sacc[1][0]);
            sacc[1][1] = fmaf(as1, xs4,  sacc[1][1]);
            sacc[1][2] = fmaf(as2, xs5,  sacc[1][2]);
            sacc[1][3] = fmaf(as3, xs6,  sacc[1][3]);
            sacc[2][0] = fmaf(as0, xs5,  sacc[2][0]);
            sacc[2][1] = fmaf(as1, xs6,  sacc[2][1]);
            sacc[2][2] = fmaf(as2, xs7,  sacc[2][2]);
            sacc[2][3] = fmaf(as3, xs8,  sacc[2][3]);
            sacc[3][0] = fmaf(as0, xs7,  sacc[3][0]);
            sacc[3][1] = fmaf(as1, xs8,  sacc[3][1]);
            sacc[3][2] = fmaf(as2, xs9,  sacc[3][2]);
            sacc[3][3] = fmaf(as3, xs10, sacc[3][3]);
        }
    }

    // ---------------- epilogue ----------------
    const float scale = 1.0f / (float)C_;
    ull scale2;
    asm("mov.b64 %0, {%1, %1};" : "=l"(scale2) : "f"(scale));

    #pragma unroll
    for (int m = 0; m < 5; ++m) {           // even dj = 2m
        const int d = di * 9 + 2 * m;
        mul2(eacc[m][0], scale2);
        mul2(eacc[m][1], scale2);
        float* o = out + (((size_t)b * 81 + d) * H_ + (h0 + r)) * W_ + w0 + wbase;
        ulonglong2 v = make_ulonglong2(eacc[m][0], eacc[m][1]);
        *reinterpret_cast<ulonglong2*>(o) = v;
    }
    #pragma unroll
    for (int m = 0; m < 4; ++m) {           // odd dj = 2m+1
        const int d = di * 9 + 2 * m + 1;
        float4 v;
        v.x = sacc[m][0] * scale;
        v.y = sacc[m][1] * scale;
        v.z = sacc[m][2] * scale;
        v.w = sacc[m][3] * scale;
        float* o = out + (((size_t)b * 81 + d) * H_ + (h0 + r)) * W_ + w0 + wbase;
        *reinterpret_cast<float4*>(o) = v;
    }
}

extern "C" void kernel_launch(void* const* d_in, const int* in_sizes, int n_in,
                              void* d_out, int out_size) {
    const float* x1 = (const float*)d_in[0];
    const float* x2 = (const float*)d_in[1];
    float* out = (float*)d_out;

    static bool attr_set = false;
    if (!attr_set) {
        cudaFuncSetAttribute(corr_kernel,
                             cudaFuncAttributeMaxDynamicSharedMemorySize,
                             SMEM_FLOATS * (int)sizeof(float));
        attr_set = true;
    }

    dim3 grid(W_ / TW, H_ / TH, B_);   // (6, 24, 4)
    corr_kernel<<<grid, NTHREADS, SMEM_FLOATS * sizeof(float)>>>(x1, x2, out);
}

// round 9
// speedup vs baseline: 1.0849x; 1.0849x over previous
#include <cuda_runtime.h>
#include <cuda_bf16.h>
#include <cstdint>

// Correlation cost volume:
// out[b, 9*i+j, h, w] = (1/C) * sum_c x1[b,c,h,w] * x2[b,c,h+i-4,w+j-4]
// B=4, C=256, H=96, W=192, 9x9 grid, zero padding.
// R9 = R6's proven pipeline (CH=8, issue-then-wait1, two syncs, TW=32,
// 16B cp.async, conflict-free LDS.128) + R7's verified scalar-odd compute
// (FFMA2 evens, scalar FFMA odds, no MOVs) + occupancy 3.

#define B_ 4
#define C_ 256
#define H_ 96
#define W_ 192
#define HW_ (H_ * W_)
#define TH 4
#define TW 32
#define PW 4
#define CH 8
#define NCHUNK (C_ / CH)          // 32
#define X2ROWS 12
#define X2STR 56                  // conflict-free LDS.128
#define X1STR 40                  // conflict-free LDS.128
#define X2BUF (CH * X2ROWS * X2STR)   // 5376 floats per buffer
#define X1BUF (CH * TH * X1STR)       // 1280 floats per buffer
#define SMEM_FLOATS (2 * X2BUF + 2 * X1BUF)   // 13312 floats = 53248 B
#define NTHREADS 288
#define CHUNK_ELEMS (CH * HW_)
#define X2CHSTRB (X2ROWS * X2STR * 4)
#define X1CHSTRB (TH * X1STR * 4)
#define X2BUFB (X2BUF * 4)
#define X1BUFB (X1BUF * 4)

typedef unsigned long long ull;

__device__ __forceinline__ void cp_async16(uint32_t dst, const float* src, int sz) {
    asm volatile("cp.async.cg.shared.global [%0], [%1], 16, %2;\n"
                 :: "r"(dst), "l"(src), "r"(sz));
}
__device__ __forceinline__ void cp_commit() {
    asm volatile("cp.async.commit_group;\n");
}
__device__ __forceinline__ void cp_wait1() {
    asm volatile("cp.async.wait_group 1;\n");
}
__device__ __forceinline__ void fma2(ull& acc, ull a, ull b) {
    asm("fma.rn.f32x2 %0, %1, %2, %0;" : "+l"(acc) : "l"(a), "l"(b));
}
__device__ __forceinline__ void mul2(ull& acc, ull s) {
    asm("mul.rn.f32x2 %0, %0, %1;" : "+l"(acc) : "l"(s));
}
__device__ __forceinline__ float LOF(ull v) { return __uint_as_float((uint32_t)v); }
__device__ __forceinline__ float HIF(ull v) { return __uint_as_float((uint32_t)(v >> 32)); }

__global__ __launch_bounds__(NTHREADS, 3)
void corr_kernel(const float* __restrict__ x1,
                 const float* __restrict__ x2,
                 float* __restrict__ out) {
    extern __shared__ float smem[];
    float* sx2 = smem;                 // [2][CH][12][56]
    float* sx1 = smem + 2 * X2BUF;     // [2][CH][4][40]

    const int w0 = blockIdx.x * TW;
    const int h0 = blockIdx.y * TH;
    const int b  = blockIdx.z;

    const int tid  = threadIdx.x;
    const int di   = tid >> 5;
    const int lane = tid & 31;
    const int r    = lane & 3;
    const int wg   = lane >> 2;
    const int wbase = wg * PW;
    const int rdi  = r + di;

    const float* x1g = x1 + (size_t)b * C_ * HW_;
    const float* x2g = x2 + (size_t)b * C_ * HW_;

    const uint32_t sx2_u = (uint32_t)__cvta_generic_to_shared(sx2);
    const uint32_t sx1_u = (uint32_t)__cvta_generic_to_shared(sx1);

    // ---------------- affine loader precompute ----------------
    // x2: CH*12 = 96 rows x 12 float4 = 1152 jobs. qid = tid + 288*s (s=0..3),
    // 288 = 24*12: q = tid%12 fixed, rowid = tid/12 + 24*s ->
    //   rr = (tid/12)%12 fixed, c = (tid/12)/12 + 2*s.
    const int r0  = tid / 12;          // 0..23
    const int qx  = tid - r0 * 12;     // 0..11
    const int c0  = r0 / 12;           // 0..1
    const int rr  = r0 - c0 * 12;      // 0..11
    const int gh  = h0 + rr - 4;
    const int gw0 = w0 - 8 + 4 * qx;
    const bool ok = ((unsigned)gh < (unsigned)H_) && (gw0 >= 0) && (gw0 <= W_ - 4);
    const int x2size = ok ? 16 : 0;
    const float* x2s0 = ok ? (x2g + ((size_t)c0 * H_ + gh) * W_ + gw0) : x2g;
    const uint32_t x2d0 = sx2_u + (uint32_t)(((c0 * X2ROWS + rr) * X2STR + 4 * qx) * 4);

    // x1: CH*4 = 32 rows x 8 float4 = 256 jobs, threads 0..255.
    const bool do_x1 = (tid < 256);
    const int c1  = tid >> 5;
    const int rr1 = (tid >> 3) & 3;
    const int q1  = tid & 7;
    const float* x1s0 = x1g + ((size_t)c1 * H_ + (h0 + rr1)) * W_ + w0 + 4 * q1;
    const uint32_t x1d0 = sx1_u + (uint32_t)(((c1 * TH + rr1) * X1STR + 4 * q1) * 4);

    // ---------------- accumulators ----------------
    ull  eacc[5][2];     // even dj (0,2,4,6,8) x pixel-pair (01, 23)
    float sacc[4][4];    // odd  dj (1,3,5,7)  x pixel (0..3)
    #pragma unroll
    for (int m = 0; m < 5; ++m) { eacc[m][0] = 0ull; eacc[m][1] = 0ull; }
    #pragma unroll
    for (int m = 0; m < 4; ++m)
        #pragma unroll
        for (int k = 0; k < 4; ++k) sacc[m][k] = 0.0f;

    // ---- prologue: load chunk 0 into buffer 0 ----
    {
        const float* s2 = x2s0;
        uint32_t d2 = x2d0;
        #pragma unroll
        for (int s = 0; s < 4; ++s) {
            cp_async16(d2, s2, x2size);
            s2 += 2 * HW_;
            d2 += 2 * X2CHSTRB;
        }
        if (do_x1) cp_async16(x1d0, x1s0, 16);
    }
    cp_commit();

    // ---------------- main pipelined loop (R6 ordering) ----------------
    for (int it = 0; it < NCHUNK; ++it) {
        // issue loads for chunk it+1 into the other buffer
        if (it + 1 < NCHUNK) {
            const int chOff = (it + 1) * CHUNK_ELEMS;
            const uint32_t bo2 = ((it + 1) & 1) ? (uint32_t)X2BUFB : 0u;
            const uint32_t bo1 = ((it + 1) & 1) ? (uint32_t)X1BUFB : 0u;
            const float* s2 = x2s0 + chOff;
            uint32_t d2 = x2d0 + bo2;
            #pragma unroll
            for (int s = 0; s < 4; ++s) {
                cp_async16(d2, s2, x2size);
                s2 += 2 * HW_;
                d2 += 2 * X2CHSTRB;
            }
            if (do_x1) cp_async16(x1d0 + bo1, x1s0 + chOff, 16);
        }
        cp_commit();
        cp_wait1();          // chunk `it` resident (its group + newer one out)
        __syncthreads();

        const float* cx1 = sx1 + (it & 1) * X1BUF + r * X1STR + wbase;
        const float* cx2 = sx2 + (it & 1) * X2BUF + rdi * X2STR + (wbase + 4);

        #pragma unroll
        for (int c = 0; c < CH; ++c) {
            const ulonglong2 A  = *reinterpret_cast<const ulonglong2*>(cx1 + c * (TH * X1STR));
            const ulonglong2 E0 = *reinterpret_cast<const ulonglong2*>(cx2 + c * (X2ROWS * X2STR));
            const ulonglong2 E1 = *reinterpret_cast<const ulonglong2*>(cx2 + c * (X2ROWS * X2STR) + 4);
            const ulonglong2 E2 = *reinterpret_cast<const ulonglong2*>(cx2 + c * (X2ROWS * X2STR) + 8);
            const ull a0 = A.x,  a1 = A.y;
            const ull e0 = E0.x, e1 = E0.y;
            const ull e2 = E1.x, e3 = E1.y;
            const ull e4 = E2.x, e5 = E2.y;

            // even dj = 2m: packed FFMA2 on natural pairs
            fma2(eacc[0][0], a0, e0); fma2(eacc[0][1], a1, e1);
            fma2(eacc[1][0], a0, e1); fma2(eacc[1][1], a1, e2);
            fma2(eacc[2][0], a0, e2); fma2(eacc[2][1], a1, e3);
            fma2(eacc[3][0], a0, e3); fma2(eacc[3][1], a1, e4);
            fma2(eacc[4][0], a0, e4); fma2(eacc[4][1], a1, e5);

            // odd dj = 2m+1: scalar FFMA on free half-register refs (no MOVs)
            const float as0 = LOF(a0), as1 = HIF(a0), as2 = LOF(a1), as3 = HIF(a1);
            const float xs1 = HIF(e0), xs2 = LOF(e1), xs3 = HIF(e1), xs4 = LOF(e2);
            const float xs5 = HIF(e2), xs6 = LOF(e3), xs7 = HIF(e3), xs8 = LOF(e4);
            const float xs9 = HIF(e4), xs10 = LOF(e5);
            sacc[0][0] = fmaf(as0, xs1,  sacc[0][0]);
            sacc[0][1] = fmaf(as1, xs2,  sacc[0][1]);
            sacc[0][2] = fmaf(as2, xs3,  sacc[0][2]);
            sacc[0][3] = fmaf(as3, xs4,  sacc[0][3]);
            sacc[1][0] = fmaf(as0, xs3,  sacc[1][0]);
            sacc[1][1] = fmaf(as1, xs4,  sacc[1][1]);
            sacc[1][2] = fmaf(as2, xs5,  sacc[1][2]);
            sacc[1][3] = fmaf(as3, xs6,  sacc[1][3]);
            sacc[2][0] = fmaf(as0, xs5,  sacc[2][0]);
            sacc[2][1] = fmaf(as1, xs6,  sacc[2][1]);
            sacc[2][2] = fmaf(as2, xs7,  sacc[2][2]);
            sacc[2][3] = fmaf(as3, xs8,  sacc[2][3]);
            sacc[3][0] = fmaf(as0, xs7,  sacc[3][0]);
            sacc[3][1] = fmaf(as1, xs8,  sacc[3][1]);
            sacc[3][2] = fmaf(as2, xs9,  sacc[3][2]);
            sacc[3][3] = fmaf(as3, xs10, sacc[3][3]);
        }
        __syncthreads();   // buffer (it&1) free for reuse at iter it+1
    }

    // ---------------- epilogue ----------------
    const float scale = 1.0f / (float)C_;
    ull scale2;
    asm("mov.b64 %0, {%1, %1};" : "=l"(scale2) : "f"(scale));

    #pragma unroll
    for (int m = 0; m < 5; ++m) {           // even dj = 2m
        const int d = di * 9 + 2 * m;
        mul2(eacc[m][0], scale2);
        mul2(eacc[m][1], scale2);
        float* o = out + (((size_t)b * 81 + d) * H_ + (h0 + r)) * W_ + w0 + wbase;
        ulonglong2 v = make_ulonglong2(eacc[m][0], eacc[m][1]);
        *reinterpret_cast<ulonglong2*>(o) = v;
    }
    #pragma unroll
    for (int m = 0; m < 4; ++m) {           // odd dj = 2m+1
        const int d = di * 9 + 2 * m + 1;
        float4 v;
        v.x = sacc[m][0] * scale;
        v.y = sacc[m][1] * scale;
        v.z = sacc[m][2] * scale;
        v.w = sacc[m][3] * scale;
        float* o = out + (((size_t)b * 81 + d) * H_ + (h0 + r)) * W_ + w0 + wbase;
        *reinterpret_cast<float4*>(o) = v;
    }
}

extern "C" void kernel_launch(void* const* d_in, const int* in_sizes, int n_in,
                              void* d_out, int out_size) {
    const float* x1 = (const float*)d_in[0];
    const float* x2 = (const float*)d_in[1];
    float* out = (float*)d_out;

    static bool attr_set = false;
    if (!attr_set) {
        cudaFuncSetAttribute(corr_kernel,
                             cudaFuncAttributeMaxDynamicSharedMemorySize,
                             SMEM_FLOATS * (int)sizeof(float));
        attr_set = true;
    }

    dim3 grid(W_ / TW, H_ / TH, B_);   // (6, 24, 4)
    corr_kernel<<<grid, NTHREADS, SMEM_FLOATS * sizeof(float)>>>(x1, x2, out);
}

// round 10
// speedup vs baseline: 1.6854x; 1.5534x over previous
#include <cuda_runtime.h>
#include <cuda_bf16.h>
#include <cstdint>

// Correlation cost volume:
// out[b, 9*i+j, h, w] = (1/C) * sum_c x1[b,c,h,w] * x2[b,c,h+i-4,w+j-4]
// B=4, C=256, H=96, W=192, 9x9 grid, zero padding.
// R10 = R2's proven scalar-FFMA compute (best fma-pipe efficiency) +
// R9's compact affine loader + occupancy 3 + 32-bit shared addressing.

#define B_ 4
#define C_ 256
#define H_ 96
#define W_ 192
#define HW_ (H_ * W_)
#define TH 4
#define TW 32
#define PW 4
#define CH 8
#define NCHUNK (C_ / CH)          // 32
#define X2ROWS 12
#define X2STR 56                  // conflict-free LDS.128
#define X1STR 40                  // conflict-free LDS.128
#define X2BUF (CH * X2ROWS * X2STR)   // 5376 floats per buffer
#define X1BUF (CH * TH * X1STR)       // 1280 floats per buffer
#define SMEM_FLOATS (2 * X2BUF + 2 * X1BUF)   // 13312 floats = 53248 B
#define NTHREADS 288
#define CHUNK_ELEMS (CH * HW_)
#define X2CHSTRB (X2ROWS * X2STR * 4)   // 2688
#define X1CHSTRB (TH * X1STR * 4)       // 640
#define X2BUFB (X2BUF * 4)
#define X1BUFB (X1BUF * 4)

__device__ __forceinline__ void cp_async16(uint32_t dst, const float* src, int sz) {
    asm volatile("cp.async.cg.shared.global [%0], [%1], 16, %2;\n"
                 :: "r"(dst), "l"(src), "r"(sz));
}
__device__ __forceinline__ void cp_commit() {
    asm volatile("cp.async.commit_group;\n");
}
__device__ __forceinline__ void cp_wait1() {
    asm volatile("cp.async.wait_group 1;\n");
}
__device__ __forceinline__ float4 lds128(uint32_t a) {
    float4 v;
    asm("ld.shared.v4.f32 {%0, %1, %2, %3}, [%4];"
        : "=f"(v.x), "=f"(v.y), "=f"(v.z), "=f"(v.w) : "r"(a));
    return v;
}

__global__ __launch_bounds__(NTHREADS, 3)
void corr_kernel(const float* __restrict__ x1,
                 const float* __restrict__ x2,
                 float* __restrict__ out) {
    extern __shared__ float smem[];

    const int w0 = blockIdx.x * TW;
    const int h0 = blockIdx.y * TH;
    const int b  = blockIdx.z;

    const int tid  = threadIdx.x;
    const int di   = tid >> 5;
    const int lane = tid & 31;
    const int r    = lane & 3;
    const int wg   = lane >> 2;
    const int wbase = wg * PW;
    const int rdi  = r + di;

    const float* x1g = x1 + (size_t)b * C_ * HW_;
    const float* x2g = x2 + (size_t)b * C_ * HW_;

    const uint32_t sx2_u = (uint32_t)__cvta_generic_to_shared(smem);
    const uint32_t sx1_u = sx2_u + (uint32_t)(2 * X2BUFB);

    // ---------------- affine loader precompute (proven in R9) ----------------
    // x2: CH*12 = 96 rows x 12 float4 = 1152 jobs; qid = tid + 288*s (s=0..3).
    // 288 = 24*12: q = tid%12 fixed, rr = (tid/12)%12 fixed, c = (tid/12)/12 + 2s.
    const int r0  = tid / 12;
    const int qx  = tid - r0 * 12;
    const int c0  = r0 / 12;          // 0..1
    const int rr  = r0 - c0 * 12;     // 0..11
    const int gh  = h0 + rr - 4;
    const int gw0 = w0 - 8 + 4 * qx;
    const bool ok = ((unsigned)gh < (unsigned)H_) && (gw0 >= 0) && (gw0 <= W_ - 4);
    const int x2size = ok ? 16 : 0;
    const float* x2s0 = ok ? (x2g + ((size_t)c0 * H_ + gh) * W_ + gw0) : x2g;
    const uint32_t x2d0 = sx2_u + (uint32_t)(((c0 * X2ROWS + rr) * X2STR + 4 * qx) * 4);

    // x1: CH*4 = 32 rows x 8 float4 = 256 jobs, threads 0..255.
    const bool do_x1 = (tid < 256);
    const int c1  = tid >> 5;
    const int rr1 = (tid >> 3) & 3;
    const int q1  = tid & 7;
    const float* x1s0 = x1g + ((size_t)c1 * H_ + (h0 + rr1)) * W_ + w0 + 4 * q1;
    const uint32_t x1d0 = sx1_u + (uint32_t)(((c1 * TH + rr1) * X1STR + 4 * q1) * 4);

    // ---------------- accumulators (R2 layout: scalar fp32) ----------------
    float acc[9][PW];
    #pragma unroll
    for (int dj = 0; dj < 9; ++dj)
        #pragma unroll
        for (int k = 0; k < PW; ++k) acc[dj][k] = 0.0f;

    // ---- prologue: chunk 0 -> buffer 0 ----
    {
        const float* s2 = x2s0;
        uint32_t d2 = x2d0;
        #pragma unroll
        for (int s = 0; s < 4; ++s) {
            cp_async16(d2, s2, x2size);
            s2 += 2 * HW_;
            d2 += 2 * X2CHSTRB;
        }
        if (do_x1) cp_async16(x1d0, x1s0, 16);
    }
    cp_commit();

    // ---------------- main pipelined loop (R2/R6 ordering) ----------------
    for (int it = 0; it < NCHUNK; ++it) {
        if (it + 1 < NCHUNK) {
            const int chOff = (it + 1) * CHUNK_ELEMS;
            const uint32_t bo2 = ((it + 1) & 1) ? (uint32_t)X2BUFB : 0u;
            const uint32_t bo1 = ((it + 1) & 1) ? (uint32_t)X1BUFB : 0u;
            const float* s2 = x2s0 + chOff;
            uint32_t d2 = x2d0 + bo2;
            #pragma unroll
            for (int s = 0; s < 4; ++s) {
                cp_async16(d2, s2, x2size);
                s2 += 2 * HW_;
                d2 += 2 * X2CHSTRB;
            }
            if (do_x1) cp_async16(x1d0 + bo1, x1s0 + chOff, 16);
        }
        cp_commit();
        cp_wait1();
        __syncthreads();

        uint32_t p1 = sx1_u + (uint32_t)((it & 1) * X1BUFB)
                    + (uint32_t)((r * X1STR + wbase) * 4);
        uint32_t p2 = sx2_u + (uint32_t)((it & 1) * X2BUFB)
                    + (uint32_t)((rdi * X2STR + wbase + 4) * 4);

        #pragma unroll
        for (int c = 0; c < CH; ++c) {
            const float4 av = lds128(p1);
            const float4 v0 = lds128(p2);
            const float4 v1 = lds128(p2 + 16);
            const float4 v2 = lds128(p2 + 32);
            p1 += X1CHSTRB;
            p2 += X2CHSTRB;
            float a[PW] = {av.x, av.y, av.z, av.w};
            float xw[12] = {v0.x, v0.y, v0.z, v0.w,
                            v1.x, v1.y, v1.z, v1.w,
                            v2.x, v2.y, v2.z, v2.w};
            #pragma unroll
            for (int dj = 0; dj < 9; ++dj)
                #pragma unroll
                for (int k = 0; k < PW; ++k)
                    acc[dj][k] = fmaf(a[k], xw[dj + k], acc[dj][k]);
        }
        __syncthreads();
    }

    // ---------------- epilogue (R2) ----------------
    const float scale = 1.0f / (float)C_;
    #pragma unroll
    for (int dj = 0; dj < 9; ++dj) {
        const int d = di * 9 + dj;
        float4 v;
        v.x = acc[dj][0] * scale;
        v.y = acc[dj][1] * scale;
        v.z = acc[dj][2] * scale;
        v.w = acc[dj][3] * scale;
        float* o = out + (((size_t)b * 81 + d) * H_ + (h0 + r)) * W_ + w0 + wbase;
        *reinterpret_cast<float4*>(o) = v;
    }
}

extern "C" void kernel_launch(void* const* d_in, const int* in_sizes, int n_in,
                              void* d_out, int out_size) {
    const float* x1 = (const float*)d_in[0];
    const float* x2 = (const float*)d_in[1];
    float* out = (float*)d_out;

    static bool attr_set = false;
    if (!attr_set) {
        cudaFuncSetAttribute(corr_kernel,
                             cudaFuncAttributeMaxDynamicSharedMemorySize,
                             SMEM_FLOATS * (int)sizeof(float));
        attr_set = true;
    }

    dim3 grid(W_ / TW, H_ / TH, B_);   // (6, 24, 4)
    corr_kernel<<<grid, NTHREADS, SMEM_FLOATS * sizeof(float)>>>(x1, x2, out);
}